// round 14
// baseline (speedup 1.0000x reference)
#include <cuda_runtime.h>
#include <cuda_fp16.h>
#include <cstdint>

#define N_NODES 100000
#define N_EDGES 1600000
#define IN_DIM  256
#define HID     128
#define OUT_DIM 64

#define SCAN_CHUNK 1024
#define N_CHUNKS   ((N_NODES + SCAN_CHUNK - 1) / SCAN_CHUNK)   // 98

// Scratch (static device allocations — no cudaMalloc allowed)
__device__ __half g_h16[(size_t)N_NODES * HID];    // ping
__device__ __half g_p16[(size_t)N_NODES * HID];    // pong
__device__ float  g_dinv[N_NODES];
__device__ int    g_src[N_EDGES];
__device__ int    g_dst[N_EDGES];
__device__ int    g_degi[N_NODES];
__device__ int    g_rowstart[N_NODES];
__device__ int    g_cursor[N_NODES];
__device__ int    g_csr_src[N_EDGES];
__device__ int    g_bsum[N_CHUNKS];
__device__ int    g_is64;

// fp16 transposed weights: Wt[n][k]
__device__ __half g_wt1[HID * IN_DIM];
__device__ __half g_wt2[HID * HID];
__device__ __half g_wtf1[HID * HID];
__device__ __half g_wtf2[OUT_DIM * HID];

// ======================= edge prologue =====================================
__global__ void k_detect(const int* __restrict__ ei32) {
    if (threadIdx.x == 0 && blockIdx.x == 0) {
        int all0 = 1;
        for (int i = 0; i < 256; i++)
            if (ei32[2 * i + 1] != 0) { all0 = 0; break; }
        g_is64 = all0;
    }
}

__global__ void k_zero_deg() {
    int i = blockIdx.x * blockDim.x + threadIdx.x;
    if (i < N_NODES) g_degi[i] = 0;
}

__global__ void k_convert_count(const void* __restrict__ ei) {
    int e = blockIdx.x * blockDim.x + threadIdx.x;
    if (e >= N_EDGES) return;
    int s, d;
    if (g_is64) {
        const long long* p = (const long long*)ei;
        s = (int)p[e];
        d = (int)p[e + N_EDGES];
    } else {
        const int* p = (const int*)ei;
        s = p[e];
        d = p[e + N_EDGES];
    }
    s = min(max(s, 0), N_NODES - 1);
    d = min(max(d, 0), N_NODES - 1);
    g_src[e] = s;
    g_dst[e] = d;
    atomicAdd(&g_degi[d], 1);
}

__global__ void k_scan_sum() {
    __shared__ int sh[SCAN_CHUNK];
    int i = blockIdx.x * SCAN_CHUNK + threadIdx.x;
    sh[threadIdx.x] = (i < N_NODES) ? g_degi[i] : 0;
    __syncthreads();
    for (int off = SCAN_CHUNK / 2; off > 0; off >>= 1) {
        if (threadIdx.x < off) sh[threadIdx.x] += sh[threadIdx.x + off];
        __syncthreads();
    }
    if (threadIdx.x == 0) g_bsum[blockIdx.x] = sh[0];
}

__global__ void k_scan_top() {
    __shared__ int sh[N_CHUNKS];
    if (threadIdx.x < N_CHUNKS) sh[threadIdx.x] = g_bsum[threadIdx.x];
    __syncthreads();
    if (threadIdx.x == 0) {
        int run = 0;
        for (int i = 0; i < N_CHUNKS; i++) { int v = sh[i]; sh[i] = run; run += v; }
    }
    __syncthreads();
    if (threadIdx.x < N_CHUNKS) g_bsum[threadIdx.x] = sh[threadIdx.x];
}

__global__ void k_scan_fin() {
    __shared__ int sh[SCAN_CHUNK];
    int i = blockIdx.x * SCAN_CHUNK + threadIdx.x;
    int v = (i < N_NODES) ? g_degi[i] : 0;
    sh[threadIdx.x] = v;
    __syncthreads();
    for (int off = 1; off < SCAN_CHUNK; off <<= 1) {
        int t = (threadIdx.x >= off) ? sh[threadIdx.x - off] : 0;
        __syncthreads();
        sh[threadIdx.x] += t;
        __syncthreads();
    }
    if (i < N_NODES) {
        int excl = g_bsum[blockIdx.x] + sh[threadIdx.x] - v;
        g_rowstart[i] = excl;
        g_cursor[i]   = excl;
        g_dinv[i]     = rsqrtf(1.0f + (float)g_degi[i]);
    }
}

__global__ void k_bucket() {
    int e = blockIdx.x * blockDim.x + threadIdx.x;
    if (e >= N_EDGES) return;
    int d = g_dst[e];
    int p = atomicAdd(&g_cursor[d], 1);
    g_csr_src[p] = g_src[e];
}

// ================= weight transpose+convert: W[K][N] -> Wt[n][k] fp16 ======
__global__ void k_wt(const float* __restrict__ W, __half* __restrict__ Wt,
                     int K, int N) {
    int idx = blockIdx.x * blockDim.x + threadIdx.x;
    if (idx >= K * N) return;
    int n = idx / K;
    int k = idx - n * K;
    Wt[(size_t)n * K + k] = __float2half(W[(size_t)k * N + n]);
}

// ============================ mma helper ===================================
__device__ __forceinline__ void mma_fp16(float d[4], const unsigned a[4], const unsigned b[2]) {
    asm volatile(
        "mma.sync.aligned.m16n8k16.row.col.f32.f16.f16.f32 "
        "{%0,%1,%2,%3}, {%4,%5,%6,%7}, {%8,%9}, {%0,%1,%2,%3};"
        : "+f"(d[0]), "+f"(d[1]), "+f"(d[2]), "+f"(d[3])
        : "r"(a[0]), "r"(a[1]), "r"(a[2]), "r"(a[3]), "r"(b[0]), "r"(b[1]));
}

__device__ __forceinline__ void h16_load4(const __half* base, size_t row,
                                          int lane, float f[4]) {
    uint2 u = *(const uint2*)(base + row * HID + lane * 4);
    __half2 p0 = *(__half2*)&u.x;
    __half2 p1 = *(__half2*)&u.y;
    float2 a = __half22float2(p0);
    float2 b = __half22float2(p1);
    f[0] = a.x; f[1] = a.y; f[2] = b.x; f[3] = b.y;
}

// ============ GEMM1: fp32 A, BK=64 loop (known-good geometry) ==============
__global__ void __launch_bounds__(256)
k_gemm_f32(const float* __restrict__ A, const __half* __restrict__ Wt,
           __half* __restrict__ C, int M, int K)
{
    constexpr int BN = 128, BM = 128, BK = 64;
    constexpr int WN = BN / 2;
    constexpr int NT = WN / 8;
    constexpr int RS = 36;

    __shared__ uint32_t As[BM * RS];
    __shared__ uint32_t Bs[BN * RS];

    const int tid  = threadIdx.x;
    const int wid  = tid >> 5;
    const int lane = tid & 31;
    const int wm   = wid & 3;
    const int wn   = wid >> 2;
    const int bm   = blockIdx.x * BM;
    const int lq   = lane & 3;
    const int lr   = lane >> 2;

    float acc[2][NT][4];
#pragma unroll
    for (int tm = 0; tm < 2; tm++)
#pragma unroll
        for (int tn = 0; tn < NT; tn++)
#pragma unroll
            for (int i = 0; i < 4; i++) acc[tm][tn][i] = 0.0f;

    for (int k0 = 0; k0 < K; k0 += BK) {
#pragma unroll
        for (int p = 0; p < 8; p++) {
            int idx = p * 256 + tid;
            int r   = idx >> 4;
            int f4  = idx & 15;
            float4 v = make_float4(0.f, 0.f, 0.f, 0.f);
            if (bm + r < M)
                v = *(const float4*)&A[(size_t)(bm + r) * K + k0 + f4 * 4];
            __half2 h01 = __floats2half2_rn(v.x, v.y);
            __half2 h23 = __floats2half2_rn(v.z, v.w);
            As[r * RS + f4 * 2]     = *(uint32_t*)&h01;
            As[r * RS + f4 * 2 + 1] = *(uint32_t*)&h23;
        }
#pragma unroll
        for (int p = 0; p < 4; p++) {
            int idx = p * 256 + tid;
            int n   = idx >> 3;
            int u   = idx & 7;
            uint4 v = *(const uint4*)(Wt + (size_t)n * K + k0 + u * 8);
            *(uint4*)&Bs[n * RS + u * 4] = v;
        }
        __syncthreads();

#pragma unroll
        for (int ks = 0; ks < 4; ks++) {
            const int kp = ks * 8;
            unsigned af[2][4];
            unsigned bf[NT][2];
#pragma unroll
            for (int tm = 0; tm < 2; tm++) {
                int r = wm * 32 + tm * 16 + lr;
                af[tm][0] = As[r * RS + kp + lq];
                af[tm][1] = As[(r + 8) * RS + kp + lq];
                af[tm][2] = As[r * RS + kp + lq + 4];
                af[tm][3] = As[(r + 8) * RS + kp + lq + 4];
            }
#pragma unroll
            for (int tn = 0; tn < NT; tn++) {
                int c = wn * WN + tn * 8 + lr;
                bf[tn][0] = Bs[c * RS + kp + lq];
                bf[tn][1] = Bs[c * RS + kp + lq + 4];
            }
#pragma unroll
            for (int tm = 0; tm < 2; tm++)
#pragma unroll
                for (int tn = 0; tn < NT; tn++)
                    mma_fp16(acc[tm][tn], af[tm], bf[tn]);
        }
        __syncthreads();
    }

#pragma unroll
    for (int tm = 0; tm < 2; tm++) {
        int r0 = bm + wm * 32 + tm * 16 + lr;
#pragma unroll
        for (int half = 0; half < 2; half++) {
            int r = r0 + half * 8;
            if (r >= M) continue;
#pragma unroll
            for (int tn = 0; tn < NT; tn++) {
                int c = wn * WN + tn * 8 + lq * 2;
                __half2 hv = __floats2half2_rn(acc[tm][tn][half * 2 + 0],
                                               acc[tm][tn][half * 2 + 1]);
                *(__half2*)(C + (size_t)r * BN + c) = hv;
            }
        }
    }
}

// ========== FUSED: aggregate 128 rows into smem -> single-shot GEMM ========
// Phase 1: each warp aggregates 16 nodes; As[r] = relu(agg_row(n) + preB)
// Phase 2: mma over K=128, epilogue (optional bias/relu) -> fp16 out.
template <bool EPI_BIAS, bool EPI_RELU>
__global__ void __launch_bounds__(256)
k_aggemm(const __half* __restrict__ Hin,
         const int* __restrict__ csr_src, const int* __restrict__ rowstart,
         const int* __restrict__ degi, const float* __restrict__ dinv,
         const float* __restrict__ preB,
         const __half* __restrict__ Wt, const float* __restrict__ epiB,
         __half* __restrict__ Cout, int M)
{
    constexpr int BN = HID, BM = 128, K = HID;
    constexpr int WN = BN / 2;
    constexpr int NT = WN / 8;
    constexpr int RS = 68;

    __shared__ uint32_t As[BM * RS];
    __shared__ uint32_t Bs[BN * RS];

    const int tid  = threadIdx.x;
    const int wid  = tid >> 5;
    const int lane = tid & 31;
    const int wm   = wid & 3;
    const int wn   = wid >> 2;
    const int bm   = blockIdx.x * BM;
    const int lq   = lane & 3;
    const int lr   = lane >> 2;

    // ---- B tile first (independent; overlaps with gather latency) ----
#pragma unroll
    for (int p = 0; p < 8; p++) {
        int idx = p * 256 + tid;
        int n   = idx >> 4;
        int u   = idx & 15;
        uint4 v = *(const uint4*)(Wt + (size_t)n * K + u * 8);
        *(uint4*)&Bs[n * RS + u * 4] = v;
    }

    // ---- Phase 1: aggregate. Warp w owns rows w*16 .. w*16+15 ----
    float pb0 = preB[lane * 4 + 0];
    float pb1 = preB[lane * 4 + 1];
    float pb2 = preB[lane * 4 + 2];
    float pb3 = preB[lane * 4 + 3];

    for (int i = 0; i < 16; i++) {
        int r = wid * 16 + i;
        int n = bm + r;
        float4 acc = make_float4(0.f, 0.f, 0.f, 0.f);
        if (n < M) {
            float di = dinv[n];
            float f[4];
            h16_load4(Hin, (size_t)n, lane, f);
            float s0 = di * di;
            acc = make_float4(f[0] * s0, f[1] * s0, f[2] * s0, f[3] * s0);

            int beg = rowstart[n];
            int cnt = degi[n];
            int j = 0;
            for (; j + 2 <= cnt; j += 2) {
                int sa = csr_src[beg + j];
                int sb = csr_src[beg + j + 1];
                float na = dinv[sa] * di;
                float nb = dinv[sb] * di;
                float fa[4], fb[4];
                h16_load4(Hin, (size_t)sa, lane, fa);
                h16_load4(Hin, (size_t)sb, lane, fb);
                acc.x = fmaf(fa[0], na, acc.x); acc.y = fmaf(fa[1], na, acc.y);
                acc.z = fmaf(fa[2], na, acc.z); acc.w = fmaf(fa[3], na, acc.w);
                acc.x = fmaf(fb[0], nb, acc.x); acc.y = fmaf(fb[1], nb, acc.y);
                acc.z = fmaf(fb[2], nb, acc.z); acc.w = fmaf(fb[3], nb, acc.w);
            }
            if (j < cnt) {
                int sa = csr_src[beg + j];
                float na = dinv[sa] * di;
                float fa[4];
                h16_load4(Hin, (size_t)sa, lane, fa);
                acc.x = fmaf(fa[0], na, acc.x); acc.y = fmaf(fa[1], na, acc.y);
                acc.z = fmaf(fa[2], na, acc.z); acc.w = fmaf(fa[3], na, acc.w);
            }
            acc.x = fmaxf(acc.x + pb0, 0.f);
            acc.y = fmaxf(acc.y + pb1, 0.f);
            acc.z = fmaxf(acc.z + pb2, 0.f);
            acc.w = fmaxf(acc.w + pb3, 0.f);
        }
        __half2 h01 = __floats2half2_rn(acc.x, acc.y);
        __half2 h23 = __floats2half2_rn(acc.z, acc.w);
        As[r * RS + lane * 2]     = *(uint32_t*)&h01;
        As[r * RS + lane * 2 + 1] = *(uint32_t*)&h23;
    }
    __syncthreads();

    // ---- Phase 2: single-shot GEMM over K=128 ----
    float acc[2][NT][4];
#pragma unroll
    for (int tm = 0; tm < 2; tm++)
#pragma unroll
        for (int tn = 0; tn < NT; tn++)
#pragma unroll
            for (int i = 0; i < 4; i++) acc[tm][tn][i] = 0.0f;

#pragma unroll
    for (int ks = 0; ks < 8; ks++) {
        const int kp = ks * 8;
        unsigned af[2][4];
        unsigned bf[NT][2];
#pragma unroll
        for (int tm = 0; tm < 2; tm++) {
            int r = wm * 32 + tm * 16 + lr;
            af[tm][0] = As[r * RS + kp + lq];
            af[tm][1] = As[(r + 8) * RS + kp + lq];
            af[tm][2] = As[r * RS + kp + lq + 4];
            af[tm][3] = As[(r + 8) * RS + kp + lq + 4];
        }
#pragma unroll
        for (int tn = 0; tn < NT; tn++) {
            int c = wn * WN + tn * 8 + lr;
            bf[tn][0] = Bs[c * RS + kp + lq];
            bf[tn][1] = Bs[c * RS + kp + lq + 4];
        }
#pragma unroll
        for (int tm = 0; tm < 2; tm++)
#pragma unroll
            for (int tn = 0; tn < NT; tn++)
                mma_fp16(acc[tm][tn], af[tm], bf[tn]);
    }

    // ---- epilogue -> fp16 ----
#pragma unroll
    for (int tm = 0; tm < 2; tm++) {
        int r0 = bm + wm * 32 + tm * 16 + lr;
#pragma unroll
        for (int half = 0; half < 2; half++) {
            int r = r0 + half * 8;
            if (r >= M) continue;
#pragma unroll
            for (int tn = 0; tn < NT; tn++) {
                int c = wn * WN + tn * 8 + lq * 2;
                float v0 = acc[tm][tn][half * 2 + 0];
                float v1 = acc[tm][tn][half * 2 + 1];
                if (EPI_BIAS) { v0 += epiB[c]; v1 += epiB[c + 1]; }
                if (EPI_RELU) { v0 = fmaxf(v0, 0.f); v1 = fmaxf(v1, 0.f); }
                __half2 hv = __floats2half2_rn(v0, v1);
                *(__half2*)(Cout + (size_t)r * BN + c) = hv;
            }
        }
    }
}

// ========= GEMM4: fp16 A, K=128 single-shot, fp32 out ======================
template <int BN>
__global__ void __launch_bounds__(256)
k_gemm_hh(const __half* __restrict__ A16, const __half* __restrict__ Wt,
          const float* __restrict__ epiB, float* __restrict__ C, int M)
{
    constexpr int K = 128, BM = 128;
    constexpr int WN = BN / 2;
    constexpr int NT = WN / 8;
    constexpr int RS = 68;

    __shared__ uint32_t As[BM * RS];
    __shared__ uint32_t Bs[BN * RS];

    const int tid  = threadIdx.x;
    const int wid  = tid >> 5;
    const int lane = tid & 31;
    const int wm   = wid & 3;
    const int wn   = wid >> 2;
    const int bm   = blockIdx.x * BM;
    const int lq   = lane & 3;
    const int lr   = lane >> 2;

#pragma unroll
    for (int p = 0; p < 8; p++) {
        int idx = p * 256 + tid;
        int r   = idx >> 4;
        int u   = idx & 15;
        uint4 v = make_uint4(0u, 0u, 0u, 0u);
        if (bm + r < M)
            v = *(const uint4*)(A16 + (size_t)(bm + r) * K + u * 8);
        *(uint4*)&As[r * RS + u * 4] = v;
    }
    constexpr int BU = BN * 16;
#pragma unroll
    for (int p = 0; p < BU / 256; p++) {
        int idx = p * 256 + tid;
        int n   = idx >> 4;
        int u   = idx & 15;
        uint4 v = *(const uint4*)(Wt + (size_t)n * K + u * 8);
        *(uint4*)&Bs[n * RS + u * 4] = v;
    }
    __syncthreads();

    float acc[2][NT][4];
#pragma unroll
    for (int tm = 0; tm < 2; tm++)
#pragma unroll
        for (int tn = 0; tn < NT; tn++)
#pragma unroll
            for (int i = 0; i < 4; i++) acc[tm][tn][i] = 0.0f;

#pragma unroll
    for (int ks = 0; ks < 8; ks++) {
        const int kp = ks * 8;
        unsigned af[2][4];
        unsigned bf[NT][2];
#pragma unroll
        for (int tm = 0; tm < 2; tm++) {
            int r = wm * 32 + tm * 16 + lr;
            af[tm][0] = As[r * RS + kp + lq];
            af[tm][1] = As[(r + 8) * RS + kp + lq];
            af[tm][2] = As[r * RS + kp + lq + 4];
            af[tm][3] = As[(r + 8) * RS + kp + lq + 4];
        }
#pragma unroll
        for (int tn = 0; tn < NT; tn++) {
            int c = wn * WN + tn * 8 + lr;
            bf[tn][0] = Bs[c * RS + kp + lq];
            bf[tn][1] = Bs[c * RS + kp + lq + 4];
        }
#pragma unroll
        for (int tm = 0; tm < 2; tm++)
#pragma unroll
            for (int tn = 0; tn < NT; tn++)
                mma_fp16(acc[tm][tn], af[tm], bf[tn]);
    }

#pragma unroll
    for (int tm = 0; tm < 2; tm++) {
        int r0 = bm + wm * 32 + tm * 16 + lr;
#pragma unroll
        for (int half = 0; half < 2; half++) {
            int r = r0 + half * 8;
            if (r >= M) continue;
#pragma unroll
            for (int tn = 0; tn < NT; tn++) {
                int c = wn * WN + tn * 8 + lq * 2;
                float v0 = acc[tm][tn][half * 2 + 0] + epiB[c];
                float v1 = acc[tm][tn][half * 2 + 1] + epiB[c + 1];
                C[(size_t)r * BN + c]     = v0;
                C[(size_t)r * BN + c + 1] = v1;
            }
        }
    }
}

// ---------------------------------------------------------------------------
extern "C" void kernel_launch(void* const* d_in, const int* in_sizes, int n_in,
                              void* d_out, int out_size)
{
    const float* x   = (const float*)d_in[0];
    const void*  ei  = d_in[1];
    const float* W1  = (const float*)d_in[2];
    const float* b1  = (const float*)d_in[3];
    const float* W2  = (const float*)d_in[4];
    const float* b2  = (const float*)d_in[5];
    const float* Wf1 = (const float*)d_in[6];
    const float* bf1 = (const float*)d_in[7];
    const float* Wf2 = (const float*)d_in[8];
    const float* bf2 = (const float*)d_in[9];
    float* out = (float*)d_out;

    float *dinv;
    __half *h16, *p16, *wt1, *wt2, *wtf1, *wtf2;
    int *csr_src, *rowstart, *degi;
    cudaGetSymbolAddress((void**)&h16,      g_h16);
    cudaGetSymbolAddress((void**)&p16,      g_p16);
    cudaGetSymbolAddress((void**)&dinv,     g_dinv);
    cudaGetSymbolAddress((void**)&csr_src,  g_csr_src);
    cudaGetSymbolAddress((void**)&rowstart, g_rowstart);
    cudaGetSymbolAddress((void**)&degi,     g_degi);
    cudaGetSymbolAddress((void**)&wt1,      g_wt1);
    cudaGetSymbolAddress((void**)&wt2,      g_wt2);
    cudaGetSymbolAddress((void**)&wtf1,     g_wtf1);
    cudaGetSymbolAddress((void**)&wtf2,     g_wtf2);

    static cudaStream_t s2 = nullptr;
    static cudaEvent_t evFork = nullptr, evJoin = nullptr;
    if (!s2) {
        cudaStreamCreateWithFlags(&s2, cudaStreamNonBlocking);
        cudaEventCreateWithFlags(&evFork, cudaEventDisableTiming);
        cudaEventCreateWithFlags(&evJoin, cudaEventDisableTiming);
    }

    const int gm = (N_NODES + 127) / 128;

    // --- fork ---
    cudaEventRecord(evFork, 0);
    cudaStreamWaitEvent(s2, evFork, 0);

    // Keep GEMM1 at kernel-launch index 3 (ncu -s 5 lands there).
    k_detect<<<1, 32, 0, s2>>>((const int*)ei);                      // 0
    k_zero_deg<<<(N_NODES + 255) / 256, 256, 0, s2>>>();             // 1
    k_wt<<<(IN_DIM * HID + 255) / 256, 256>>>(W1, wt1, IN_DIM, HID); // 2 (s0)

    // --- GEMM1 (A fp32 = X) on stream 0, fp16 output ---             3 (s0)
    k_gemm_f32<<<gm, 256>>>(x, wt1, h16, N_NODES, IN_DIM);

    // --- rest of CSR prologue + weight converts on s2 ---
    k_convert_count<<<(N_EDGES + 255) / 256, 256, 0, s2>>>(ei);
    k_scan_sum<<<N_CHUNKS, SCAN_CHUNK, 0, s2>>>();
    k_scan_top<<<1, SCAN_CHUNK, 0, s2>>>();
    k_scan_fin<<<N_CHUNKS, SCAN_CHUNK, 0, s2>>>();
    k_bucket<<<(N_EDGES + 255) / 256, 256, 0, s2>>>();
    k_wt<<<(HID * HID + 255) / 256, 256, 0, s2>>>(W2,  wt2,  HID, HID);
    k_wt<<<(HID * HID + 255) / 256, 256, 0, s2>>>(Wf1, wtf1, HID, HID);
    k_wt<<<(HID * OUT_DIM + 255) / 256, 256, 0, s2>>>(Wf2, wtf2, HID, OUT_DIM);
    cudaEventRecord(evJoin, s2);

    // --- join: fused layers need CSR (s2) + h16 (s0) ---
    cudaStreamWaitEvent(0, evJoin, 0);

    // layer 2 fused: p16 = [relu(agg(h16) + b1)] @ W2
    k_aggemm<false, false><<<gm, 256>>>(
        h16, csr_src, rowstart, degi, dinv, b1, wt2, nullptr, p16, N_NODES);

    // layer 3 fused: h16 = relu([relu(agg(p16) + b2)] @ Wf1 + bf1)
    k_aggemm<true, true><<<gm, 256>>>(
        p16, csr_src, rowstart, degi, dinv, b2, wtf1, bf1, h16, N_NODES);

    // GEMM4: out = h16 @ Wf2 + bf2 (fp32)
    k_gemm_hh<OUT_DIM><<<gm, 256>>>(h16, wtf2, bf2, out, N_NODES);
}

// round 15
// speedup vs baseline: 1.2584x; 1.2584x over previous
#include <cuda_runtime.h>
#include <cuda_fp16.h>
#include <cstdint>

#define N_NODES 100000
#define N_EDGES 1600000
#define IN_DIM  256
#define HID     128
#define OUT_DIM 64

#define SCAN_CHUNK 1024
#define N_CHUNKS   ((N_NODES + SCAN_CHUNK - 1) / SCAN_CHUNK)   // 98

// Scratch (static device allocations — no cudaMalloc allowed)
__device__ __half g_h16[(size_t)N_NODES * HID];    // ping
__device__ __half g_p16[(size_t)N_NODES * HID];    // pong
__device__ float  g_dinv[N_NODES];
__device__ int    g_src[N_EDGES];
__device__ int    g_dst[N_EDGES];
__device__ int    g_degi[N_NODES];
__device__ int    g_rowstart[N_NODES];
__device__ int    g_cursor[N_NODES];
__device__ int    g_csr_src[N_EDGES];
__device__ int    g_bsum[N_CHUNKS];
__device__ int    g_is64;

// fp16 transposed weights: Wt[n][k]
__device__ __half g_wt1[HID * IN_DIM];
__device__ __half g_wt2[HID * HID];
__device__ __half g_wtf1[HID * HID];
__device__ __half g_wtf2[OUT_DIM * HID];

// ======================= edge prologue =====================================
__global__ void k_detect(const int* __restrict__ ei32) {
    if (threadIdx.x == 0 && blockIdx.x == 0) {
        int all0 = 1;
        for (int i = 0; i < 256; i++)
            if (ei32[2 * i + 1] != 0) { all0 = 0; break; }
        g_is64 = all0;
    }
}

__global__ void k_zero_deg() {
    int i = blockIdx.x * blockDim.x + threadIdx.x;
    if (i < N_NODES) g_degi[i] = 0;
}

__global__ void k_convert_count(const void* __restrict__ ei) {
    int e = blockIdx.x * blockDim.x + threadIdx.x;
    if (e >= N_EDGES) return;
    int s, d;
    if (g_is64) {
        const long long* p = (const long long*)ei;
        s = (int)p[e];
        d = (int)p[e + N_EDGES];
    } else {
        const int* p = (const int*)ei;
        s = p[e];
        d = p[e + N_EDGES];
    }
    s = min(max(s, 0), N_NODES - 1);
    d = min(max(d, 0), N_NODES - 1);
    g_src[e] = s;
    g_dst[e] = d;
    atomicAdd(&g_degi[d], 1);
}

__global__ void k_scan_sum() {
    __shared__ int sh[SCAN_CHUNK];
    int i = blockIdx.x * SCAN_CHUNK + threadIdx.x;
    sh[threadIdx.x] = (i < N_NODES) ? g_degi[i] : 0;
    __syncthreads();
    for (int off = SCAN_CHUNK / 2; off > 0; off >>= 1) {
        if (threadIdx.x < off) sh[threadIdx.x] += sh[threadIdx.x + off];
        __syncthreads();
    }
    if (threadIdx.x == 0) g_bsum[blockIdx.x] = sh[0];
}

__global__ void k_scan_top() {
    __shared__ int sh[N_CHUNKS];
    if (threadIdx.x < N_CHUNKS) sh[threadIdx.x] = g_bsum[threadIdx.x];
    __syncthreads();
    if (threadIdx.x == 0) {
        int run = 0;
        for (int i = 0; i < N_CHUNKS; i++) { int v = sh[i]; sh[i] = run; run += v; }
    }
    __syncthreads();
    if (threadIdx.x < N_CHUNKS) g_bsum[threadIdx.x] = sh[threadIdx.x];
}

__global__ void k_scan_fin() {
    __shared__ int sh[SCAN_CHUNK];
    int i = blockIdx.x * SCAN_CHUNK + threadIdx.x;
    int v = (i < N_NODES) ? g_degi[i] : 0;
    sh[threadIdx.x] = v;
    __syncthreads();
    for (int off = 1; off < SCAN_CHUNK; off <<= 1) {
        int t = (threadIdx.x >= off) ? sh[threadIdx.x - off] : 0;
        __syncthreads();
        sh[threadIdx.x] += t;
        __syncthreads();
    }
    if (i < N_NODES) {
        int excl = g_bsum[blockIdx.x] + sh[threadIdx.x] - v;
        g_rowstart[i] = excl;
        g_cursor[i]   = excl;
        g_dinv[i]     = rsqrtf(1.0f + (float)g_degi[i]);
    }
}

__global__ void k_bucket() {
    int e = blockIdx.x * blockDim.x + threadIdx.x;
    if (e >= N_EDGES) return;
    int d = g_dst[e];
    int p = atomicAdd(&g_cursor[d], 1);
    g_csr_src[p] = g_src[e];
}

// ================= weight transpose+convert: W[K][N] -> Wt[n][k] fp16 ======
__global__ void k_wt(const float* __restrict__ W, __half* __restrict__ Wt,
                     int K, int N) {
    int idx = blockIdx.x * blockDim.x + threadIdx.x;
    if (idx >= K * N) return;
    int n = idx / K;
    int k = idx - n * K;
    Wt[(size_t)n * K + k] = __float2half(W[(size_t)k * N + n]);
}

// ============================ mma helper ===================================
__device__ __forceinline__ void mma_fp16(float d[4], const unsigned a[4], const unsigned b[2]) {
    asm volatile(
        "mma.sync.aligned.m16n8k16.row.col.f32.f16.f16.f32 "
        "{%0,%1,%2,%3}, {%4,%5,%6,%7}, {%8,%9}, {%0,%1,%2,%3};"
        : "+f"(d[0]), "+f"(d[1]), "+f"(d[2]), "+f"(d[3])
        : "r"(a[0]), "r"(a[1]), "r"(a[2]), "r"(a[3]), "r"(b[0]), "r"(b[1]));
}

__device__ __forceinline__ void h16_load4(const __half* base, size_t row,
                                          int lane, float f[4]) {
    uint2 u = *(const uint2*)(base + row * HID + lane * 4);
    __half2 p0 = *(__half2*)&u.x;
    __half2 p1 = *(__half2*)&u.y;
    float2 a = __half22float2(p0);
    float2 b = __half22float2(p1);
    f[0] = a.x; f[1] = a.y; f[2] = b.x; f[3] = b.y;
}

// ============ GEMM1: fp32 A, BK=64 loop (known-good geometry) ==============
__global__ void __launch_bounds__(256)
k_gemm_f32(const float* __restrict__ A, const __half* __restrict__ Wt,
           __half* __restrict__ C, int M, int K)
{
    constexpr int BN = 128, BM = 128, BK = 64;
    constexpr int WN = BN / 2;
    constexpr int NT = WN / 8;
    constexpr int RS = 36;

    __shared__ uint32_t As[BM * RS];
    __shared__ uint32_t Bs[BN * RS];

    const int tid  = threadIdx.x;
    const int wid  = tid >> 5;
    const int lane = tid & 31;
    const int wm   = wid & 3;
    const int wn   = wid >> 2;
    const int bm   = blockIdx.x * BM;
    const int lq   = lane & 3;
    const int lr   = lane >> 2;

    float acc[2][NT][4];
#pragma unroll
    for (int tm = 0; tm < 2; tm++)
#pragma unroll
        for (int tn = 0; tn < NT; tn++)
#pragma unroll
            for (int i = 0; i < 4; i++) acc[tm][tn][i] = 0.0f;

    for (int k0 = 0; k0 < K; k0 += BK) {
#pragma unroll
        for (int p = 0; p < 8; p++) {
            int idx = p * 256 + tid;
            int r   = idx >> 4;
            int f4  = idx & 15;
            float4 v = make_float4(0.f, 0.f, 0.f, 0.f);
            if (bm + r < M)
                v = *(const float4*)&A[(size_t)(bm + r) * K + k0 + f4 * 4];
            __half2 h01 = __floats2half2_rn(v.x, v.y);
            __half2 h23 = __floats2half2_rn(v.z, v.w);
            As[r * RS + f4 * 2]     = *(uint32_t*)&h01;
            As[r * RS + f4 * 2 + 1] = *(uint32_t*)&h23;
        }
#pragma unroll
        for (int p = 0; p < 4; p++) {
            int idx = p * 256 + tid;
            int n   = idx >> 3;
            int u   = idx & 7;
            uint4 v = *(const uint4*)(Wt + (size_t)n * K + k0 + u * 8);
            *(uint4*)&Bs[n * RS + u * 4] = v;
        }
        __syncthreads();

#pragma unroll
        for (int ks = 0; ks < 4; ks++) {
            const int kp = ks * 8;
            unsigned af[2][4];
            unsigned bf[NT][2];
#pragma unroll
            for (int tm = 0; tm < 2; tm++) {
                int r = wm * 32 + tm * 16 + lr;
                af[tm][0] = As[r * RS + kp + lq];
                af[tm][1] = As[(r + 8) * RS + kp + lq];
                af[tm][2] = As[r * RS + kp + lq + 4];
                af[tm][3] = As[(r + 8) * RS + kp + lq + 4];
            }
#pragma unroll
            for (int tn = 0; tn < NT; tn++) {
                int c = wn * WN + tn * 8 + lr;
                bf[tn][0] = Bs[c * RS + kp + lq];
                bf[tn][1] = Bs[c * RS + kp + lq + 4];
            }
#pragma unroll
            for (int tm = 0; tm < 2; tm++)
#pragma unroll
                for (int tn = 0; tn < NT; tn++)
                    mma_fp16(acc[tm][tn], af[tm], bf[tn]);
        }
        __syncthreads();
    }

#pragma unroll
    for (int tm = 0; tm < 2; tm++) {
        int r0 = bm + wm * 32 + tm * 16 + lr;
#pragma unroll
        for (int half = 0; half < 2; half++) {
            int r = r0 + half * 8;
            if (r >= M) continue;
#pragma unroll
            for (int tn = 0; tn < NT; tn++) {
                int c = wn * WN + tn * 8 + lq * 2;
                __half2 hv = __floats2half2_rn(acc[tm][tn][half * 2 + 0],
                                               acc[tm][tn][half * 2 + 1]);
                *(__half2*)(C + (size_t)r * BN + c) = hv;
            }
        }
    }
}

// ====== gather aggregation: fp16 in, fp16 out, fused bias+relu =============
__global__ void __launch_bounds__(256)
k_aggregate(const int* __restrict__ csr_src,
            const int* __restrict__ rowstart,
            const int* __restrict__ degi,
            const __half* __restrict__ h16,
            const float* __restrict__ dinv,
            const float* __restrict__ bias,
            __half* __restrict__ agg16)
{
    int n    = (blockIdx.x * blockDim.x + threadIdx.x) >> 5;
    int lane = threadIdx.x & 31;
    if (n >= N_NODES) return;

    float di = dinv[n];
    float f[4];
    h16_load4(h16, (size_t)n, lane, f);
    float s0 = di * di;
    float4 acc = make_float4(f[0] * s0, f[1] * s0, f[2] * s0, f[3] * s0);

    int beg = rowstart[n];
    int cnt = degi[n];
    int j = 0;
    for (; j + 2 <= cnt; j += 2) {
        int sa = csr_src[beg + j];
        int sb = csr_src[beg + j + 1];
        float na = dinv[sa] * di;
        float nb = dinv[sb] * di;
        float fa[4], fb[4];
        h16_load4(h16, (size_t)sa, lane, fa);
        h16_load4(h16, (size_t)sb, lane, fb);
        acc.x = fmaf(fa[0], na, acc.x); acc.y = fmaf(fa[1], na, acc.y);
        acc.z = fmaf(fa[2], na, acc.z); acc.w = fmaf(fa[3], na, acc.w);
        acc.x = fmaf(fb[0], nb, acc.x); acc.y = fmaf(fb[1], nb, acc.y);
        acc.z = fmaf(fb[2], nb, acc.z); acc.w = fmaf(fb[3], nb, acc.w);
    }
    if (j < cnt) {
        int sa = csr_src[beg + j];
        float na = dinv[sa] * di;
        float fa[4];
        h16_load4(h16, (size_t)sa, lane, fa);
        acc.x = fmaf(fa[0], na, acc.x); acc.y = fmaf(fa[1], na, acc.y);
        acc.z = fmaf(fa[2], na, acc.z); acc.w = fmaf(fa[3], na, acc.w);
    }

    int c = lane * 4;
    acc.x = fmaxf(acc.x + bias[c + 0], 0.f);
    acc.y = fmaxf(acc.y + bias[c + 1], 0.f);
    acc.z = fmaxf(acc.z + bias[c + 2], 0.f);
    acc.w = fmaxf(acc.w + bias[c + 3], 0.f);

    __half2 o0 = __floats2half2_rn(acc.x, acc.y);
    __half2 o1 = __floats2half2_rn(acc.z, acc.w);
    uint2 u;
    u.x = *(uint32_t*)&o0;
    u.y = *(uint32_t*)&o1;
    *(uint2*)(agg16 + (size_t)n * HID + lane * 4) = u;
}

// ========= GEMM2: fp16 A, K=128 single-shot, fp16 out ======================
__global__ void __launch_bounds__(256)
k_gemm_hh(const __half* __restrict__ A16, const __half* __restrict__ Wt,
          __half* __restrict__ C, int M)
{
    constexpr int BN = 128, K = 128, BM = 128;
    constexpr int WN = BN / 2;
    constexpr int NT = WN / 8;
    constexpr int RS = 68;

    __shared__ uint32_t As[BM * RS];
    __shared__ uint32_t Bs[BN * RS];

    const int tid  = threadIdx.x;
    const int wid  = tid >> 5;
    const int lane = tid & 31;
    const int wm   = wid & 3;
    const int wn   = wid >> 2;
    const int bm   = blockIdx.x * BM;
    const int lq   = lane & 3;
    const int lr   = lane >> 2;

#pragma unroll
    for (int p = 0; p < 8; p++) {
        int idx = p * 256 + tid;
        int r   = idx >> 4;
        int u   = idx & 15;
        uint4 v = make_uint4(0u, 0u, 0u, 0u);
        if (bm + r < M)
            v = *(const uint4*)(A16 + (size_t)(bm + r) * K + u * 8);
        *(uint4*)&As[r * RS + u * 4] = v;
    }
#pragma unroll
    for (int p = 0; p < 8; p++) {
        int idx = p * 256 + tid;
        int n   = idx >> 4;
        int u   = idx & 15;
        uint4 v = *(const uint4*)(Wt + (size_t)n * K + u * 8);
        *(uint4*)&Bs[n * RS + u * 4] = v;
    }
    __syncthreads();

    float acc[2][NT][4];
#pragma unroll
    for (int tm = 0; tm < 2; tm++)
#pragma unroll
        for (int tn = 0; tn < NT; tn++)
#pragma unroll
            for (int i = 0; i < 4; i++) acc[tm][tn][i] = 0.0f;

#pragma unroll
    for (int ks = 0; ks < 8; ks++) {
        const int kp = ks * 8;
        unsigned af[2][4];
        unsigned bf[NT][2];
#pragma unroll
        for (int tm = 0; tm < 2; tm++) {
            int r = wm * 32 + tm * 16 + lr;
            af[tm][0] = As[r * RS + kp + lq];
            af[tm][1] = As[(r + 8) * RS + kp + lq];
            af[tm][2] = As[r * RS + kp + lq + 4];
            af[tm][3] = As[(r + 8) * RS + kp + lq + 4];
        }
#pragma unroll
        for (int tn = 0; tn < NT; tn++) {
            int c = wn * WN + tn * 8 + lr;
            bf[tn][0] = Bs[c * RS + kp + lq];
            bf[tn][1] = Bs[c * RS + kp + lq + 4];
        }
#pragma unroll
        for (int tm = 0; tm < 2; tm++)
#pragma unroll
            for (int tn = 0; tn < NT; tn++)
                mma_fp16(acc[tm][tn], af[tm], bf[tn]);
    }

#pragma unroll
    for (int tm = 0; tm < 2; tm++) {
        int r0 = bm + wm * 32 + tm * 16 + lr;
#pragma unroll
        for (int half = 0; half < 2; half++) {
            int r = r0 + half * 8;
            if (r >= M) continue;
#pragma unroll
            for (int tn = 0; tn < NT; tn++) {
                int c = wn * WN + tn * 8 + lq * 2;
                __half2 hv = __floats2half2_rn(acc[tm][tn][half * 2 + 0],
                                               acc[tm][tn][half * 2 + 1]);
                *(__half2*)(C + (size_t)r * BN + c) = hv;
            }
        }
    }
}

// ====== FUSED MLP head: out = [relu(A@Wf1 + bf1)] @ Wf2 + bf2 ==============
// Stage 1: A (fp16, [M,128]) x Wf1 -> 128x128 tile in regs, +bf1, relu.
// Stage 2: tile -> As (fp16, smem reuse), Wf2 -> Bs rows 0-63, mma, +bf2.
__global__ void __launch_bounds__(256)
k_gemm_mlp(const __half* __restrict__ A16, const __half* __restrict__ Wt1,
           const float* __restrict__ bf1, const __half* __restrict__ Wt2,
           const float* __restrict__ bf2, float* __restrict__ C, int M)
{
    constexpr int K = 128, BM = 128, BN1 = 128, BN2 = 64;
    constexpr int WN1 = BN1 / 2, NT1 = WN1 / 8;   // 64, 8
    constexpr int WN2 = BN2 / 2, NT2 = WN2 / 8;   // 32, 4
    constexpr int RS = 68;

    __shared__ uint32_t As[BM * RS];
    __shared__ uint32_t Bs[BN1 * RS];

    const int tid  = threadIdx.x;
    const int wid  = tid >> 5;
    const int lane = tid & 31;
    const int wm   = wid & 3;
    const int wn   = wid >> 2;
    const int bm   = blockIdx.x * BM;
    const int lq   = lane & 3;
    const int lr   = lane >> 2;

    // ---- stage-1 loads ----
#pragma unroll
    for (int p = 0; p < 8; p++) {
        int idx = p * 256 + tid;
        int r   = idx >> 4;
        int u   = idx & 15;
        uint4 v = make_uint4(0u, 0u, 0u, 0u);
        if (bm + r < M)
            v = *(const uint4*)(A16 + (size_t)(bm + r) * K + u * 8);
        *(uint4*)&As[r * RS + u * 4] = v;
    }
#pragma unroll
    for (int p = 0; p < 8; p++) {
        int idx = p * 256 + tid;
        int n   = idx >> 4;
        int u   = idx & 15;
        uint4 v = *(const uint4*)(Wt1 + (size_t)n * K + u * 8);
        *(uint4*)&Bs[n * RS + u * 4] = v;
    }
    __syncthreads();

    // ---- stage-1 mma ----
    float acc1[2][NT1][4];
#pragma unroll
    for (int tm = 0; tm < 2; tm++)
#pragma unroll
        for (int tn = 0; tn < NT1; tn++)
#pragma unroll
            for (int i = 0; i < 4; i++) acc1[tm][tn][i] = 0.0f;

#pragma unroll
    for (int ks = 0; ks < 8; ks++) {
        const int kp = ks * 8;
        unsigned af[2][4];
        unsigned bf[NT1][2];
#pragma unroll
        for (int tm = 0; tm < 2; tm++) {
            int r = wm * 32 + tm * 16 + lr;
            af[tm][0] = As[r * RS + kp + lq];
            af[tm][1] = As[(r + 8) * RS + kp + lq];
            af[tm][2] = As[r * RS + kp + lq + 4];
            af[tm][3] = As[(r + 8) * RS + kp + lq + 4];
        }
#pragma unroll
        for (int tn = 0; tn < NT1; tn++) {
            int c = wn * WN1 + tn * 8 + lr;
            bf[tn][0] = Bs[c * RS + kp + lq];
            bf[tn][1] = Bs[c * RS + kp + lq + 4];
        }
#pragma unroll
        for (int tm = 0; tm < 2; tm++)
#pragma unroll
            for (int tn = 0; tn < NT1; tn++)
                mma_fp16(acc1[tm][tn], af[tm], bf[tn]);
    }

    __syncthreads();   // everyone done reading As/Bs

    // ---- stage-1 epilogue: relu(+bf1) -> As (fp16); Wf2 -> Bs rows 0-63 ----
#pragma unroll
    for (int tm = 0; tm < 2; tm++) {
        int rl0 = wm * 32 + tm * 16 + lr;
#pragma unroll
        for (int half = 0; half < 2; half++) {
            int rl = rl0 + half * 8;
#pragma unroll
            for (int tn = 0; tn < NT1; tn++) {
                int c = wn * WN1 + tn * 8 + lq * 2;
                float v0 = fmaxf(acc1[tm][tn][half * 2 + 0] + bf1[c], 0.f);
                float v1 = fmaxf(acc1[tm][tn][half * 2 + 1] + bf1[c + 1], 0.f);
                __half2 hv = __floats2half2_rn(v0, v1);
                As[rl * RS + (c >> 1)] = *(uint32_t*)&hv;
            }
        }
    }
#pragma unroll
    for (int p = 0; p < 4; p++) {
        int idx = p * 256 + tid;
        int n   = idx >> 4;       // 0..63
        int u   = idx & 15;
        uint4 v = *(const uint4*)(Wt2 + (size_t)n * K + u * 8);
        *(uint4*)&Bs[n * RS + u * 4] = v;
    }
    __syncthreads();

    // ---- stage-2 mma: [128x128] @ Wf2^T -> [128x64] ----
    float acc2[2][NT2][4];
#pragma unroll
    for (int tm = 0; tm < 2; tm++)
#pragma unroll
        for (int tn = 0; tn < NT2; tn++)
#pragma unroll
            for (int i = 0; i < 4; i++) acc2[tm][tn][i] = 0.0f;

#pragma unroll
    for (int ks = 0; ks < 8; ks++) {
        const int kp = ks * 8;
        unsigned af[2][4];
        unsigned bf[NT2][2];
#pragma unroll
        for (int tm = 0; tm < 2; tm++) {
            int r = wm * 32 + tm * 16 + lr;
            af[tm][0] = As[r * RS + kp + lq];
            af[tm][1] = As[(r + 8) * RS + kp + lq];
            af[tm][2] = As[r * RS + kp + lq + 4];
            af[tm][3] = As[(r + 8) * RS + kp + lq + 4];
        }
#pragma unroll
        for (int tn = 0; tn < NT2; tn++) {
            int c = wn * WN2 + tn * 8 + lr;   // 0..63
            bf[tn][0] = Bs[c * RS + kp + lq];
            bf[tn][1] = Bs[c * RS + kp + lq + 4];
        }
#pragma unroll
        for (int tm = 0; tm < 2; tm++)
#pragma unroll
            for (int tn = 0; tn < NT2; tn++)
                mma_fp16(acc2[tm][tn], af[tm], bf[tn]);
    }

    // ---- stage-2 epilogue: +bf2, fp32 out ----
#pragma unroll
    for (int tm = 0; tm < 2; tm++) {
        int r0 = bm + wm * 32 + tm * 16 + lr;
#pragma unroll
        for (int half = 0; half < 2; half++) {
            int r = r0 + half * 8;
            if (r >= M) continue;
#pragma unroll
            for (int tn = 0; tn < NT2; tn++) {
                int c = wn * WN2 + tn * 8 + lq * 2;
                C[(size_t)r * OUT_DIM + c]     = acc2[tm][tn][half * 2 + 0] + bf2[c];
                C[(size_t)r * OUT_DIM + c + 1] = acc2[tm][tn][half * 2 + 1] + bf2[c + 1];
            }
        }
    }
}

// ---------------------------------------------------------------------------
extern "C" void kernel_launch(void* const* d_in, const int* in_sizes, int n_in,
                              void* d_out, int out_size)
{
    const float* x   = (const float*)d_in[0];
    const void*  ei  = d_in[1];
    const float* W1  = (const float*)d_in[2];
    const float* b1  = (const float*)d_in[3];
    const float* W2  = (const float*)d_in[4];
    const float* b2  = (const float*)d_in[5];
    const float* Wf1 = (const float*)d_in[6];
    const float* bf1 = (const float*)d_in[7];
    const float* Wf2 = (const float*)d_in[8];
    const float* bf2 = (const float*)d_in[9];
    float* out = (float*)d_out;

    float *dinv;
    __half *h16, *p16, *wt1, *wt2, *wtf1, *wtf2;
    int *csr_src, *rowstart, *degi;
    cudaGetSymbolAddress((void**)&h16,      g_h16);
    cudaGetSymbolAddress((void**)&p16,      g_p16);
    cudaGetSymbolAddress((void**)&dinv,     g_dinv);
    cudaGetSymbolAddress((void**)&csr_src,  g_csr_src);
    cudaGetSymbolAddress((void**)&rowstart, g_rowstart);
    cudaGetSymbolAddress((void**)&degi,     g_degi);
    cudaGetSymbolAddress((void**)&wt1,      g_wt1);
    cudaGetSymbolAddress((void**)&wt2,      g_wt2);
    cudaGetSymbolAddress((void**)&wtf1,     g_wtf1);
    cudaGetSymbolAddress((void**)&wtf2,     g_wtf2);

    static cudaStream_t s2 = nullptr;
    static cudaEvent_t evFork = nullptr, evJoin = nullptr;
    if (!s2) {
        cudaStreamCreateWithFlags(&s2, cudaStreamNonBlocking);
        cudaEventCreateWithFlags(&evFork, cudaEventDisableTiming);
        cudaEventCreateWithFlags(&evJoin, cudaEventDisableTiming);
    }

    const int gm = (N_NODES + 127) / 128;
    const int agg_blocks = (N_NODES * 32 + 255) / 256;

    // --- fork ---
    cudaEventRecord(evFork, 0);
    cudaStreamWaitEvent(s2, evFork, 0);

    // Keep GEMM1 at kernel-launch index 3 (ncu -s 5 lands there).
    k_detect<<<1, 32, 0, s2>>>((const int*)ei);                      // 0
    k_zero_deg<<<(N_NODES + 255) / 256, 256, 0, s2>>>();             // 1
    k_wt<<<(IN_DIM * HID + 255) / 256, 256>>>(W1, wt1, IN_DIM, HID); // 2 (s0)

    // --- GEMM1 (A fp32 = X) on stream 0, fp16 output ---             3 (s0)
    k_gemm_f32<<<gm, 256>>>(x, wt1, h16, N_NODES, IN_DIM);

    // --- rest of CSR prologue + weight converts on s2 ---
    k_convert_count<<<(N_EDGES + 255) / 256, 256, 0, s2>>>(ei);
    k_scan_sum<<<N_CHUNKS, SCAN_CHUNK, 0, s2>>>();
    k_scan_top<<<1, SCAN_CHUNK, 0, s2>>>();
    k_scan_fin<<<N_CHUNKS, SCAN_CHUNK, 0, s2>>>();
    k_bucket<<<(N_EDGES + 255) / 256, 256, 0, s2>>>();
    k_wt<<<(HID * HID + 255) / 256, 256, 0, s2>>>(W2,  wt2,  HID, HID);
    k_wt<<<(HID * HID + 255) / 256, 256, 0, s2>>>(Wf1, wtf1, HID, HID);
    k_wt<<<(HID * OUT_DIM + 255) / 256, 256, 0, s2>>>(Wf2, wtf2, HID, OUT_DIM);
    cudaEventRecord(evJoin, s2);

    // --- join: aggregation needs CSR (s2) + h16 (s0) ---
    cudaStreamWaitEvent(0, evJoin, 0);
    // agg1 = relu(aggregate(h16) + b1)
    k_aggregate<<<agg_blocks, 256>>>(csr_src, rowstart, degi, h16, dinv, b1, p16);

    // GEMM2: h16 = agg1 @ W2
    k_gemm_hh<<<gm, 256>>>(p16, wt2, h16, N_NODES);

    // agg2 = relu(aggregate(h16) + b2)
    k_aggregate<<<agg_blocks, 256>>>(csr_src, rowstart, degi, h16, dinv, b2, p16);

    // Fused MLP head: out = relu(agg2 @ Wf1 + bf1) @ Wf2 + bf2
    k_gemm_mlp<<<gm, 256>>>(p16, wtf1, bf1, wtf2, bf2, out, N_NODES);
}

// round 16
// speedup vs baseline: 1.2951x; 1.0292x over previous
#include <cuda_runtime.h>
#include <cuda_fp16.h>
#include <cstdint>

#define N_NODES 100000
#define N_EDGES 1600000
#define IN_DIM  256
#define HID     128
#define OUT_DIM 64

#define SCAN_CHUNK 1024
#define N_CHUNKS   ((N_NODES + SCAN_CHUNK - 1) / SCAN_CHUNK)   // 98

// Scratch (static device allocations — no cudaMalloc allowed)
__device__ __half g_h16[(size_t)N_NODES * HID];    // ping
__device__ __half g_p16[(size_t)N_NODES * HID];    // pong
__device__ float  g_dinv[N_NODES];
__device__ int    g_src[N_EDGES];
__device__ int    g_dst[N_EDGES];
__device__ int    g_degi[N_NODES];
__device__ int    g_rowstart[N_NODES];
__device__ int    g_cursor[N_NODES];
__device__ int    g_csr_src[N_EDGES];
__device__ int    g_bsum[N_CHUNKS];
__device__ int    g_is64;

// fp16 transposed weights: Wt[n][k]
__device__ __half g_wt1[HID * IN_DIM];
__device__ __half g_wt2[HID * HID];
__device__ __half g_wtf1[HID * HID];
__device__ __half g_wtf2[OUT_DIM * HID];

// ======================= edge prologue =====================================
__global__ void k_detect(const int* __restrict__ ei32) {
    if (threadIdx.x == 0 && blockIdx.x == 0) {
        int all0 = 1;
        for (int i = 0; i < 256; i++)
            if (ei32[2 * i + 1] != 0) { all0 = 0; break; }
        g_is64 = all0;
    }
}

__global__ void k_zero_deg() {
    int i = blockIdx.x * blockDim.x + threadIdx.x;
    if (i < N_NODES) g_degi[i] = 0;
}

__global__ void k_convert_count(const void* __restrict__ ei) {
    int e = blockIdx.x * blockDim.x + threadIdx.x;
    if (e >= N_EDGES) return;
    int s, d;
    if (g_is64) {
        const long long* p = (const long long*)ei;
        s = (int)p[e];
        d = (int)p[e + N_EDGES];
    } else {
        const int* p = (const int*)ei;
        s = p[e];
        d = p[e + N_EDGES];
    }
    s = min(max(s, 0), N_NODES - 1);
    d = min(max(d, 0), N_NODES - 1);
    g_src[e] = s;
    g_dst[e] = d;
    atomicAdd(&g_degi[d], 1);
}

__global__ void k_scan_sum() {
    __shared__ int sh[SCAN_CHUNK];
    int i = blockIdx.x * SCAN_CHUNK + threadIdx.x;
    sh[threadIdx.x] = (i < N_NODES) ? g_degi[i] : 0;
    __syncthreads();
    for (int off = SCAN_CHUNK / 2; off > 0; off >>= 1) {
        if (threadIdx.x < off) sh[threadIdx.x] += sh[threadIdx.x + off];
        __syncthreads();
    }
    if (threadIdx.x == 0) g_bsum[blockIdx.x] = sh[0];
}

__global__ void k_scan_top() {
    __shared__ int sh[N_CHUNKS];
    if (threadIdx.x < N_CHUNKS) sh[threadIdx.x] = g_bsum[threadIdx.x];
    __syncthreads();
    if (threadIdx.x == 0) {
        int run = 0;
        for (int i = 0; i < N_CHUNKS; i++) { int v = sh[i]; sh[i] = run; run += v; }
    }
    __syncthreads();
    if (threadIdx.x < N_CHUNKS) g_bsum[threadIdx.x] = sh[threadIdx.x];
}

__global__ void k_scan_fin() {
    __shared__ int sh[SCAN_CHUNK];
    int i = blockIdx.x * SCAN_CHUNK + threadIdx.x;
    int v = (i < N_NODES) ? g_degi[i] : 0;
    sh[threadIdx.x] = v;
    __syncthreads();
    for (int off = 1; off < SCAN_CHUNK; off <<= 1) {
        int t = (threadIdx.x >= off) ? sh[threadIdx.x - off] : 0;
        __syncthreads();
        sh[threadIdx.x] += t;
        __syncthreads();
    }
    if (i < N_NODES) {
        int excl = g_bsum[blockIdx.x] + sh[threadIdx.x] - v;
        g_rowstart[i] = excl;
        g_cursor[i]   = excl;
        g_dinv[i]     = rsqrtf(1.0f + (float)g_degi[i]);
    }
}

__global__ void k_bucket() {
    int e = blockIdx.x * blockDim.x + threadIdx.x;
    if (e >= N_EDGES) return;
    int d = g_dst[e];
    int p = atomicAdd(&g_cursor[d], 1);
    g_csr_src[p] = g_src[e];
}

// ================= weight transpose+convert: W[K][N] -> Wt[n][k] fp16 ======
__global__ void k_wt(const float* __restrict__ W, __half* __restrict__ Wt,
                     int K, int N) {
    int idx = blockIdx.x * blockDim.x + threadIdx.x;
    if (idx >= K * N) return;
    int n = idx / K;
    int k = idx - n * K;
    Wt[(size_t)n * K + k] = __float2half(W[(size_t)k * N + n]);
}

// ============================ mma helper ===================================
__device__ __forceinline__ void mma_fp16(float d[4], const unsigned a[4], const unsigned b[2]) {
    asm volatile(
        "mma.sync.aligned.m16n8k16.row.col.f32.f16.f16.f32 "
        "{%0,%1,%2,%3}, {%4,%5,%6,%7}, {%8,%9}, {%0,%1,%2,%3};"
        : "+f"(d[0]), "+f"(d[1]), "+f"(d[2]), "+f"(d[3])
        : "r"(a[0]), "r"(a[1]), "r"(a[2]), "r"(a[3]), "r"(b[0]), "r"(b[1]));
}

__device__ __forceinline__ void h16_acc(const __half* base, int row, int lane,
                                        float norm, float4& acc) {
    uint2 u = *(const uint2*)(base + (size_t)row * HID + lane * 4);
    __half2 p0 = *(__half2*)&u.x;
    __half2 p1 = *(__half2*)&u.y;
    float2 a = __half22float2(p0);
    float2 b = __half22float2(p1);
    acc.x = fmaf(a.x, norm, acc.x);
    acc.y = fmaf(a.y, norm, acc.y);
    acc.z = fmaf(b.x, norm, acc.z);
    acc.w = fmaf(b.y, norm, acc.w);
}

// ============ GEMM1: fp32 A, BK=64 loop (known-good geometry) ==============
__global__ void __launch_bounds__(256)
k_gemm_f32(const float* __restrict__ A, const __half* __restrict__ Wt,
           __half* __restrict__ C, int M, int K)
{
    constexpr int BN = 128, BM = 128, BK = 64;
    constexpr int WN = BN / 2;
    constexpr int NT = WN / 8;
    constexpr int RS = 36;

    __shared__ uint32_t As[BM * RS];
    __shared__ uint32_t Bs[BN * RS];

    const int tid  = threadIdx.x;
    const int wid  = tid >> 5;
    const int lane = tid & 31;
    const int wm   = wid & 3;
    const int wn   = wid >> 2;
    const int bm   = blockIdx.x * BM;
    const int lq   = lane & 3;
    const int lr   = lane >> 2;

    float acc[2][NT][4];
#pragma unroll
    for (int tm = 0; tm < 2; tm++)
#pragma unroll
        for (int tn = 0; tn < NT; tn++)
#pragma unroll
            for (int i = 0; i < 4; i++) acc[tm][tn][i] = 0.0f;

    for (int k0 = 0; k0 < K; k0 += BK) {
#pragma unroll
        for (int p = 0; p < 8; p++) {
            int idx = p * 256 + tid;
            int r   = idx >> 4;
            int f4  = idx & 15;
            float4 v = make_float4(0.f, 0.f, 0.f, 0.f);
            if (bm + r < M)
                v = *(const float4*)&A[(size_t)(bm + r) * K + k0 + f4 * 4];
            __half2 h01 = __floats2half2_rn(v.x, v.y);
            __half2 h23 = __floats2half2_rn(v.z, v.w);
            As[r * RS + f4 * 2]     = *(uint32_t*)&h01;
            As[r * RS + f4 * 2 + 1] = *(uint32_t*)&h23;
        }
#pragma unroll
        for (int p = 0; p < 4; p++) {
            int idx = p * 256 + tid;
            int n   = idx >> 3;
            int u   = idx & 7;
            uint4 v = *(const uint4*)(Wt + (size_t)n * K + k0 + u * 8);
            *(uint4*)&Bs[n * RS + u * 4] = v;
        }
        __syncthreads();

#pragma unroll
        for (int ks = 0; ks < 4; ks++) {
            const int kp = ks * 8;
            unsigned af[2][4];
            unsigned bf[NT][2];
#pragma unroll
            for (int tm = 0; tm < 2; tm++) {
                int r = wm * 32 + tm * 16 + lr;
                af[tm][0] = As[r * RS + kp + lq];
                af[tm][1] = As[(r + 8) * RS + kp + lq];
                af[tm][2] = As[r * RS + kp + lq + 4];
                af[tm][3] = As[(r + 8) * RS + kp + lq + 4];
            }
#pragma unroll
            for (int tn = 0; tn < NT; tn++) {
                int c = wn * WN + tn * 8 + lr;
                bf[tn][0] = Bs[c * RS + kp + lq];
                bf[tn][1] = Bs[c * RS + kp + lq + 4];
            }
#pragma unroll
            for (int tm = 0; tm < 2; tm++)
#pragma unroll
                for (int tn = 0; tn < NT; tn++)
                    mma_fp16(acc[tm][tn], af[tm], bf[tn]);
        }
        __syncthreads();
    }

#pragma unroll
    for (int tm = 0; tm < 2; tm++) {
        int r0 = bm + wm * 32 + tm * 16 + lr;
#pragma unroll
        for (int half = 0; half < 2; half++) {
            int r = r0 + half * 8;
            if (r >= M) continue;
#pragma unroll
            for (int tn = 0; tn < NT; tn++) {
                int c = wn * WN + tn * 8 + lq * 2;
                __half2 hv = __floats2half2_rn(acc[tm][tn][half * 2 + 0],
                                               acc[tm][tn][half * 2 + 1]);
                *(__half2*)(C + (size_t)r * BN + c) = hv;
            }
        }
    }
}

// ====== gather aggregation: lane-parallel index fetch + shfl broadcast =====
// One warp per node. Neighbor indices AND their dinv fetched once by lanes
// (coalesced), broadcast via shfl; row gathers issued in independent groups
// of 4. Fused relu(+bias) epilogue, fp16 out.
__global__ void __launch_bounds__(256)
k_aggregate(const int* __restrict__ csr_src,
            const int* __restrict__ rowstart,
            const int* __restrict__ degi,
            const __half* __restrict__ h16,
            const float* __restrict__ dinv,
            const float* __restrict__ bias,
            __half* __restrict__ agg16)
{
    int n    = (blockIdx.x * blockDim.x + threadIdx.x) >> 5;
    int lane = threadIdx.x & 31;
    if (n >= N_NODES) return;

    float di = dinv[n];
    float4 acc;
    {
        uint2 u = *(const uint2*)(h16 + (size_t)n * HID + lane * 4);
        __half2 p0 = *(__half2*)&u.x;
        __half2 p1 = *(__half2*)&u.y;
        float2 a = __half22float2(p0);
        float2 b = __half22float2(p1);
        float s0 = di * di;
        acc = make_float4(a.x * s0, a.y * s0, b.x * s0, b.y * s0);
    }

    int beg = rowstart[n];
    int cnt = degi[n];

    for (int base = 0; base < cnt; base += 32) {
        int m = min(cnt - base, 32);
        // lane-parallel: fetch up to 32 indices + their dinv in ONE round trip
        int   myi = (lane < m) ? csr_src[beg + base + lane] : 0;
        float myn = (lane < m) ? dinv[myi] * di : 0.f;

        int j = 0;
        for (; j + 4 <= m; j += 4) {
            int s0 = __shfl_sync(0xFFFFFFFFu, myi, j + 0);
            int s1 = __shfl_sync(0xFFFFFFFFu, myi, j + 1);
            int s2 = __shfl_sync(0xFFFFFFFFu, myi, j + 2);
            int s3 = __shfl_sync(0xFFFFFFFFu, myi, j + 3);
            float n0 = __shfl_sync(0xFFFFFFFFu, myn, j + 0);
            float n1 = __shfl_sync(0xFFFFFFFFu, myn, j + 1);
            float n2 = __shfl_sync(0xFFFFFFFFu, myn, j + 2);
            float n3 = __shfl_sync(0xFFFFFFFFu, myn, j + 3);
            // 4 independent gathers (ptxas front-batches the LDGs)
            uint2 u0 = *(const uint2*)(h16 + (size_t)s0 * HID + lane * 4);
            uint2 u1 = *(const uint2*)(h16 + (size_t)s1 * HID + lane * 4);
            uint2 u2 = *(const uint2*)(h16 + (size_t)s2 * HID + lane * 4);
            uint2 u3 = *(const uint2*)(h16 + (size_t)s3 * HID + lane * 4);
#define ACC4(U, NRM) { \
            __half2 p0 = *(__half2*)&U.x; __half2 p1 = *(__half2*)&U.y; \
            float2 aa = __half22float2(p0); float2 bb = __half22float2(p1); \
            acc.x = fmaf(aa.x, NRM, acc.x); acc.y = fmaf(aa.y, NRM, acc.y); \
            acc.z = fmaf(bb.x, NRM, acc.z); acc.w = fmaf(bb.y, NRM, acc.w); }
            ACC4(u0, n0); ACC4(u1, n1); ACC4(u2, n2); ACC4(u3, n3);
        }
        for (; j < m; j++) {
            int   s0 = __shfl_sync(0xFFFFFFFFu, myi, j);
            float n0 = __shfl_sync(0xFFFFFFFFu, myn, j);
            h16_acc(h16, s0, lane, n0, acc);
        }
    }

    int c = lane * 4;
    acc.x = fmaxf(acc.x + bias[c + 0], 0.f);
    acc.y = fmaxf(acc.y + bias[c + 1], 0.f);
    acc.z = fmaxf(acc.z + bias[c + 2], 0.f);
    acc.w = fmaxf(acc.w + bias[c + 3], 0.f);

    __half2 o0 = __floats2half2_rn(acc.x, acc.y);
    __half2 o1 = __floats2half2_rn(acc.z, acc.w);
    uint2 u;
    u.x = *(uint32_t*)&o0;
    u.y = *(uint32_t*)&o1;
    *(uint2*)(agg16 + (size_t)n * HID + lane * 4) = u;
}

// ========= GEMM2: fp16 A, K=128 single-shot, fp16 out ======================
__global__ void __launch_bounds__(256)
k_gemm_hh(const __half* __restrict__ A16, const __half* __restrict__ Wt,
          __half* __restrict__ C, int M)
{
    constexpr int BN = 128, K = 128, BM = 128;
    constexpr int WN = BN / 2;
    constexpr int NT = WN / 8;
    constexpr int RS = 68;

    __shared__ uint32_t As[BM * RS];
    __shared__ uint32_t Bs[BN * RS];

    const int tid  = threadIdx.x;
    const int wid  = tid >> 5;
    const int lane = tid & 31;
    const int wm   = wid & 3;
    const int wn   = wid >> 2;
    const int bm   = blockIdx.x * BM;
    const int lq   = lane & 3;
    const int lr   = lane >> 2;

#pragma unroll
    for (int p = 0; p < 8; p++) {
        int idx = p * 256 + tid;
        int r   = idx >> 4;
        int u   = idx & 15;
        uint4 v = make_uint4(0u, 0u, 0u, 0u);
        if (bm + r < M)
            v = *(const uint4*)(A16 + (size_t)(bm + r) * K + u * 8);
        *(uint4*)&As[r * RS + u * 4] = v;
    }
#pragma unroll
    for (int p = 0; p < 8; p++) {
        int idx = p * 256 + tid;
        int n   = idx >> 4;
        int u   = idx & 15;
        uint4 v = *(const uint4*)(Wt + (size_t)n * K + u * 8);
        *(uint4*)&Bs[n * RS + u * 4] = v;
    }
    __syncthreads();

    float acc[2][NT][4];
#pragma unroll
    for (int tm = 0; tm < 2; tm++)
#pragma unroll
        for (int tn = 0; tn < NT; tn++)
#pragma unroll
            for (int i = 0; i < 4; i++) acc[tm][tn][i] = 0.0f;

#pragma unroll
    for (int ks = 0; ks < 8; ks++) {
        const int kp = ks * 8;
        unsigned af[2][4];
        unsigned bf[NT][2];
#pragma unroll
        for (int tm = 0; tm < 2; tm++) {
            int r = wm * 32 + tm * 16 + lr;
            af[tm][0] = As[r * RS + kp + lq];
            af[tm][1] = As[(r + 8) * RS + kp + lq];
            af[tm][2] = As[r * RS + kp + lq + 4];
            af[tm][3] = As[(r + 8) * RS + kp + lq + 4];
        }
#pragma unroll
        for (int tn = 0; tn < NT; tn++) {
            int c = wn * WN + tn * 8 + lr;
            bf[tn][0] = Bs[c * RS + kp + lq];
            bf[tn][1] = Bs[c * RS + kp + lq + 4];
        }
#pragma unroll
        for (int tm = 0; tm < 2; tm++)
#pragma unroll
            for (int tn = 0; tn < NT; tn++)
                mma_fp16(acc[tm][tn], af[tm], bf[tn]);
    }

#pragma unroll
    for (int tm = 0; tm < 2; tm++) {
        int r0 = bm + wm * 32 + tm * 16 + lr;
#pragma unroll
        for (int half = 0; half < 2; half++) {
            int r = r0 + half * 8;
            if (r >= M) continue;
#pragma unroll
            for (int tn = 0; tn < NT; tn++) {
                int c = wn * WN + tn * 8 + lq * 2;
                __half2 hv = __floats2half2_rn(acc[tm][tn][half * 2 + 0],
                                               acc[tm][tn][half * 2 + 1]);
                *(__half2*)(C + (size_t)r * BN + c) = hv;
            }
        }
    }
}

// ====== FUSED MLP head: out = [relu(A@Wf1 + bf1)] @ Wf2 + bf2 ==============
__global__ void __launch_bounds__(256)
k_gemm_mlp(const __half* __restrict__ A16, const __half* __restrict__ Wt1,
           const float* __restrict__ bf1, const __half* __restrict__ Wt2,
           const float* __restrict__ bf2, float* __restrict__ C, int M)
{
    constexpr int K = 128, BM = 128, BN1 = 128, BN2 = 64;
    constexpr int WN1 = BN1 / 2, NT1 = WN1 / 8;
    constexpr int WN2 = BN2 / 2, NT2 = WN2 / 8;
    constexpr int RS = 68;

    __shared__ uint32_t As[BM * RS];
    __shared__ uint32_t Bs[BN1 * RS];

    const int tid  = threadIdx.x;
    const int wid  = tid >> 5;
    const int lane = tid & 31;
    const int wm   = wid & 3;
    const int wn   = wid >> 2;
    const int bm   = blockIdx.x * BM;
    const int lq   = lane & 3;
    const int lr   = lane >> 2;

#pragma unroll
    for (int p = 0; p < 8; p++) {
        int idx = p * 256 + tid;
        int r   = idx >> 4;
        int u   = idx & 15;
        uint4 v = make_uint4(0u, 0u, 0u, 0u);
        if (bm + r < M)
            v = *(const uint4*)(A16 + (size_t)(bm + r) * K + u * 8);
        *(uint4*)&As[r * RS + u * 4] = v;
    }
#pragma unroll
    for (int p = 0; p < 8; p++) {
        int idx = p * 256 + tid;
        int n   = idx >> 4;
        int u   = idx & 15;
        uint4 v = *(const uint4*)(Wt1 + (size_t)n * K + u * 8);
        *(uint4*)&Bs[n * RS + u * 4] = v;
    }
    __syncthreads();

    float acc1[2][NT1][4];
#pragma unroll
    for (int tm = 0; tm < 2; tm++)
#pragma unroll
        for (int tn = 0; tn < NT1; tn++)
#pragma unroll
            for (int i = 0; i < 4; i++) acc1[tm][tn][i] = 0.0f;

#pragma unroll
    for (int ks = 0; ks < 8; ks++) {
        const int kp = ks * 8;
        unsigned af[2][4];
        unsigned bf[NT1][2];
#pragma unroll
        for (int tm = 0; tm < 2; tm++) {
            int r = wm * 32 + tm * 16 + lr;
            af[tm][0] = As[r * RS + kp + lq];
            af[tm][1] = As[(r + 8) * RS + kp + lq];
            af[tm][2] = As[r * RS + kp + lq + 4];
            af[tm][3] = As[(r + 8) * RS + kp + lq + 4];
        }
#pragma unroll
        for (int tn = 0; tn < NT1; tn++) {
            int c = wn * WN1 + tn * 8 + lr;
            bf[tn][0] = Bs[c * RS + kp + lq];
            bf[tn][1] = Bs[c * RS + kp + lq + 4];
        }
#pragma unroll
        for (int tm = 0; tm < 2; tm++)
#pragma unroll
            for (int tn = 0; tn < NT1; tn++)
                mma_fp16(acc1[tm][tn], af[tm], bf[tn]);
    }

    __syncthreads();

#pragma unroll
    for (int tm = 0; tm < 2; tm++) {
        int rl0 = wm * 32 + tm * 16 + lr;
#pragma unroll
        for (int half = 0; half < 2; half++) {
            int rl = rl0 + half * 8;
#pragma unroll
            for (int tn = 0; tn < NT1; tn++) {
                int c = wn * WN1 + tn * 8 + lq * 2;
                float v0 = fmaxf(acc1[tm][tn][half * 2 + 0] + bf1[c], 0.f);
                float v1 = fmaxf(acc1[tm][tn][half * 2 + 1] + bf1[c + 1], 0.f);
                __half2 hv = __floats2half2_rn(v0, v1);
                As[rl * RS + (c >> 1)] = *(uint32_t*)&hv;
            }
        }
    }
#pragma unroll
    for (int p = 0; p < 4; p++) {
        int idx = p * 256 + tid;
        int n   = idx >> 4;
        int u   = idx & 15;
        uint4 v = *(const uint4*)(Wt2 + (size_t)n * K + u * 8);
        *(uint4*)&Bs[n * RS + u * 4] = v;
    }
    __syncthreads();

    float acc2[2][NT2][4];
#pragma unroll
    for (int tm = 0; tm < 2; tm++)
#pragma unroll
        for (int tn = 0; tn < NT2; tn++)
#pragma unroll
            for (int i = 0; i < 4; i++) acc2[tm][tn][i] = 0.0f;

#pragma unroll
    for (int ks = 0; ks < 8; ks++) {
        const int kp = ks * 8;
        unsigned af[2][4];
        unsigned bf[NT2][2];
#pragma unroll
        for (int tm = 0; tm < 2; tm++) {
            int r = wm * 32 + tm * 16 + lr;
            af[tm][0] = As[r * RS + kp + lq];
            af[tm][1] = As[(r + 8) * RS + kp + lq];
            af[tm][2] = As[r * RS + kp + lq + 4];
            af[tm][3] = As[(r + 8) * RS + kp + lq + 4];
        }
#pragma unroll
        for (int tn = 0; tn < NT2; tn++) {
            int c = wn * WN2 + tn * 8 + lr;
            bf[tn][0] = Bs[c * RS + kp + lq];
            bf[tn][1] = Bs[c * RS + kp + lq + 4];
        }
#pragma unroll
        for (int tm = 0; tm < 2; tm++)
#pragma unroll
            for (int tn = 0; tn < NT2; tn++)
                mma_fp16(acc2[tm][tn], af[tm], bf[tn]);
    }

#pragma unroll
    for (int tm = 0; tm < 2; tm++) {
        int r0 = bm + wm * 32 + tm * 16 + lr;
#pragma unroll
        for (int half = 0; half < 2; half++) {
            int r = r0 + half * 8;
            if (r >= M) continue;
#pragma unroll
            for (int tn = 0; tn < NT2; tn++) {
                int c = wn * WN2 + tn * 8 + lq * 2;
                C[(size_t)r * OUT_DIM + c]     = acc2[tm][tn][half * 2 + 0] + bf2[c];
                C[(size_t)r * OUT_DIM + c + 1] = acc2[tm][tn][half * 2 + 1] + bf2[c + 1];
            }
        }
    }
}

// ---------------------------------------------------------------------------
extern "C" void kernel_launch(void* const* d_in, const int* in_sizes, int n_in,
                              void* d_out, int out_size)
{
    const float* x   = (const float*)d_in[0];
    const void*  ei  = d_in[1];
    const float* W1  = (const float*)d_in[2];
    const float* b1  = (const float*)d_in[3];
    const float* W2  = (const float*)d_in[4];
    const float* b2  = (const float*)d_in[5];
    const float* Wf1 = (const float*)d_in[6];
    const float* bf1 = (const float*)d_in[7];
    const float* Wf2 = (const float*)d_in[8];
    const float* bf2 = (const float*)d_in[9];
    float* out = (float*)d_out;

    float *dinv;
    __half *h16, *p16, *wt1, *wt2, *wtf1, *wtf2;
    int *csr_src, *rowstart, *degi;
    cudaGetSymbolAddress((void**)&h16,      g_h16);
    cudaGetSymbolAddress((void**)&p16,      g_p16);
    cudaGetSymbolAddress((void**)&dinv,     g_dinv);
    cudaGetSymbolAddress((void**)&csr_src,  g_csr_src);
    cudaGetSymbolAddress((void**)&rowstart, g_rowstart);
    cudaGetSymbolAddress((void**)&degi,     g_degi);
    cudaGetSymbolAddress((void**)&wt1,      g_wt1);
    cudaGetSymbolAddress((void**)&wt2,      g_wt2);
    cudaGetSymbolAddress((void**)&wtf1,     g_wtf1);
    cudaGetSymbolAddress((void**)&wtf2,     g_wtf2);

    static cudaStream_t s2 = nullptr;
    static cudaEvent_t evFork = nullptr, evJoin = nullptr;
    if (!s2) {
        cudaStreamCreateWithFlags(&s2, cudaStreamNonBlocking);
        cudaEventCreateWithFlags(&evFork, cudaEventDisableTiming);
        cudaEventCreateWithFlags(&evJoin, cudaEventDisableTiming);
    }

    const int gm = (N_NODES + 127) / 128;
    const int agg_blocks = (N_NODES * 32 + 255) / 256;

    // --- fork ---
    cudaEventRecord(evFork, 0);
    cudaStreamWaitEvent(s2, evFork, 0);

    // Keep GEMM1 at kernel-launch index 3 (ncu -s 5 lands there).
    k_detect<<<1, 32, 0, s2>>>((const int*)ei);                      // 0
    k_zero_deg<<<(N_NODES + 255) / 256, 256, 0, s2>>>();             // 1
    k_wt<<<(IN_DIM * HID + 255) / 256, 256>>>(W1, wt1, IN_DIM, HID); // 2 (s0)

    // --- GEMM1 (A fp32 = X) on stream 0, fp16 output ---             3 (s0)
    k_gemm_f32<<<gm, 256>>>(x, wt1, h16, N_NODES, IN_DIM);

    // --- rest of CSR prologue + weight converts on s2 ---
    k_convert_count<<<(N_EDGES + 255) / 256, 256, 0, s2>>>(ei);
    k_scan_sum<<<N_CHUNKS, SCAN_CHUNK, 0, s2>>>();
    k_scan_top<<<1, SCAN_CHUNK, 0, s2>>>();
    k_scan_fin<<<N_CHUNKS, SCAN_CHUNK, 0, s2>>>();
    k_bucket<<<(N_EDGES + 255) / 256, 256, 0, s2>>>();
    k_wt<<<(HID * HID + 255) / 256, 256, 0, s2>>>(W2,  wt2,  HID, HID);
    k_wt<<<(HID * HID + 255) / 256, 256, 0, s2>>>(Wf1, wtf1, HID, HID);
    k_wt<<<(HID * OUT_DIM + 255) / 256, 256, 0, s2>>>(Wf2, wtf2, HID, OUT_DIM);
    cudaEventRecord(evJoin, s2);

    // --- join: aggregation needs CSR (s2) + h16 (s0) ---
    cudaStreamWaitEvent(0, evJoin, 0);
    // agg1 = relu(aggregate(h16) + b1)
    k_aggregate<<<agg_blocks, 256>>>(csr_src, rowstart, degi, h16, dinv, b1, p16);

    // GEMM2: h16 = agg1 @ W2
    k_gemm_hh<<<gm, 256>>>(p16, wt2, h16, N_NODES);

    // agg2 = relu(aggregate(h16) + b2)
    k_aggregate<<<agg_blocks, 256>>>(csr_src, rowstart, degi, h16, dinv, b2, p16);

    // Fused MLP head: out = relu(agg2 @ Wf1 + bf1) @ Wf2 + bf2
    k_gemm_mlp<<<gm, 256>>>(p16, wtf1, bf1, wtf2, bf2, out, N_NODES);
}